// round 3
// baseline (speedup 1.0000x reference)
#include <cuda_runtime.h>

// cov[n] = R(q_n) * diag(exp(2*scal_n)) * R(q_n)^T, q_n = normalize(rot_n)
__global__ void __launch_bounds__(256) gauss_cov_kernel(
    const float4* __restrict__ rot,   // [N,4]
    const float*  __restrict__ scal,  // [N,3]
    float*        __restrict__ out,   // [N,3,3]
    int n)
{
    int i = blockIdx.x * blockDim.x + threadIdx.x;
    if (i >= n) return;

    float4 q = rot[i];
    float inv = rsqrtf(q.x*q.x + q.y*q.y + q.z*q.z + q.w*q.w);
    float w = q.x * inv, x = q.y * inv, y = q.z * inv, z = q.w * inv;

    // Rotation matrix rows (quat_to_rotmat convention from reference)
    float r00 = 1.f - 2.f*(y*y + z*z);
    float r01 = 2.f*(x*y - w*z);
    float r02 = 2.f*(x*z + w*y);
    float r10 = 2.f*(x*y + w*z);
    float r11 = 1.f - 2.f*(x*x + z*z);
    float r12 = 2.f*(y*z - w*x);
    float r20 = 2.f*(x*z - w*y);
    float r21 = 2.f*(y*z + w*x);
    float r22 = 1.f - 2.f*(x*x + y*y);

    // s^2 = exp(2*scaling_raw)
    float s0 = __expf(2.f * scal[3*i + 0]);
    float s1 = __expf(2.f * scal[3*i + 1]);
    float s2 = __expf(2.f * scal[3*i + 2]);

    // cov_ij = sum_k R_ik * R_jk * s_k^2  (symmetric)
    float c00 = r00*r00*s0 + r01*r01*s1 + r02*r02*s2;
    float c01 = r00*r10*s0 + r01*r11*s1 + r02*r12*s2;
    float c02 = r00*r20*s0 + r01*r21*s1 + r02*r22*s2;
    float c11 = r10*r10*s0 + r11*r11*s1 + r12*r12*s2;
    float c12 = r10*r20*s0 + r11*r21*s1 + r12*r22*s2;
    float c22 = r20*r20*s0 + r21*r21*s1 + r22*r22*s2;

    float* o = out + (size_t)i * 9;
    o[0] = c00; o[1] = c01; o[2] = c02;
    o[3] = c01; o[4] = c11; o[5] = c12;
    o[6] = c02; o[7] = c12; o[8] = c22;
}

extern "C" void kernel_launch(void* const* d_in, const int* in_sizes, int n_in,
                              void* d_out, int out_size)
{
    const float4* rot  = (const float4*)d_in[0];  // rotation_raw [N,4]
    const float*  scal = (const float*) d_in[1];  // scaling_raw  [N,3]
    float* out = (float*)d_out;                   // [N,3,3]
    int n = in_sizes[0] / 4;

    int threads = 256;
    int blocks = (n + threads - 1) / threads;
    gauss_cov_kernel<<<blocks, threads>>>(rot, scal, out, n);
}

// round 5
// speedup vs baseline: 2.6366x; 2.6366x over previous
#include <cuda_runtime.h>

#define TPB 256

// cov[n] = R(q_n) * diag(exp(2*scal_n)) * R(q_n)^T, q_n = normalize(rot_n)
// Fully-coalesced variant: scal staged in via float4, cov staged out via float4.
__global__ void __launch_bounds__(TPB) gauss_cov_kernel(
    const float4* __restrict__ rot,    // [N,4]
    const float*  __restrict__ scal,   // [N,3] (float4-aligned base)
    float*        __restrict__ out,    // [N,3,3]
    int n)
{
    __shared__ float s_scal[TPB * 3];   // 3072 B
    __shared__ float s_out [TPB * 9];   // 9216 B

    const int tid = threadIdx.x;
    const int blockBase = blockIdx.x * TPB;
    const bool full = (blockBase + TPB) <= n;

    // ---- stage scaling_raw: 768 floats / block, coalesced ----
    if (full) {
        const float4* sc4 = (const float4*)(scal) + (size_t)blockIdx.x * (TPB * 3 / 4);
        float4* s4 = (float4*)s_scal;
        if (tid < TPB * 3 / 4) s4[tid] = sc4[tid];
    } else {
        for (int k = tid; k < TPB * 3; k += TPB) {
            size_t g = (size_t)blockBase * 3 + k;
            if (g < (size_t)n * 3) s_scal[k] = scal[g];
        }
    }
    __syncthreads();

    const int i = blockBase + tid;
    if (i < n) {
        float4 q = rot[i];
        float inv = rsqrtf(q.x*q.x + q.y*q.y + q.z*q.z + q.w*q.w);
        float w = q.x * inv, x = q.y * inv, y = q.z * inv, z = q.w * inv;

        float r00 = 1.f - 2.f*(y*y + z*z);
        float r01 = 2.f*(x*y - w*z);
        float r02 = 2.f*(x*z + w*y);
        float r10 = 2.f*(x*y + w*z);
        float r11 = 1.f - 2.f*(x*x + z*z);
        float r12 = 2.f*(y*z - w*x);
        float r20 = 2.f*(x*z - w*y);
        float r21 = 2.f*(y*z + w*x);
        float r22 = 1.f - 2.f*(x*x + y*y);

        // s^2 = exp(2*scaling_raw); smem read stride 3 -> conflict-free
        float s0 = __expf(2.f * s_scal[3*tid + 0]);
        float s1 = __expf(2.f * s_scal[3*tid + 1]);
        float s2 = __expf(2.f * s_scal[3*tid + 2]);

        float c00 = r00*r00*s0 + r01*r01*s1 + r02*r02*s2;
        float c01 = r00*r10*s0 + r01*r11*s1 + r02*r12*s2;
        float c02 = r00*r20*s0 + r01*r21*s1 + r02*r22*s2;
        float c11 = r10*r10*s0 + r11*r11*s1 + r12*r12*s2;
        float c12 = r10*r20*s0 + r11*r21*s1 + r12*r22*s2;
        float c22 = r20*r20*s0 + r21*r21*s1 + r22*r22*s2;

        // smem write stride 9 -> conflict-free
        float* so = s_out + tid * 9;
        so[0] = c00; so[1] = c01; so[2] = c02;
        so[3] = c01; so[4] = c11; so[5] = c12;
        so[6] = c02; so[7] = c12; so[8] = c22;
    }
    __syncthreads();

    // ---- drain cov: 2304 floats = 576 float4 / block, coalesced ----
    if (full) {
        float4* o4 = (float4*)(out) + (size_t)blockIdx.x * (TPB * 9 / 4);
        const float4* s4 = (const float4*)s_out;
        #pragma unroll
        for (int k = 0; k < TPB * 9 / 4; k += TPB) {
            int idx = k + tid;
            if (idx < TPB * 9 / 4) o4[idx] = s4[idx];
        }
    } else {
        for (int k = tid; k < TPB * 9; k += TPB) {
            size_t g = (size_t)blockBase * 9 + k;
            if (g < (size_t)n * 9) out[g] = s_out[k];
        }
    }
}

extern "C" void kernel_launch(void* const* d_in, const int* in_sizes, int n_in,
                              void* d_out, int out_size)
{
    const float4* rot  = (const float4*)d_in[0];  // rotation_raw [N,4]
    const float*  scal = (const float*) d_in[1];  // scaling_raw  [N,3]
    float* out = (float*)d_out;                   // [N,3,3]
    int n = in_sizes[0] / 4;

    int blocks = (n + TPB - 1) / TPB;
    gauss_cov_kernel<<<blocks, TPB>>>(rot, scal, out, n);
}